// round 3
// baseline (speedup 1.0000x reference)
#include <cuda_runtime.h>
#include <math.h>
#include <stdint.h>

#define B_SZ   256
#define T_SZ   512
#define HIDN   300
#define VOCAB  50000
#define GN     2400      // [Va | Vb] columns
#define GK     300
#define GKPAD  304
#define GNPAD  2432
#define NBLK   120       // persistent LSTM blocks (4 row tiles x 30 unit tiles)

// -------- device scratch (allocation-free rule: static __device__ arrays) -----
__device__ __align__(16) float g_V[(size_t)VOCAB * GN];   // 480 MB: per-vocab gate tables
__device__ __align__(16) float g_B[GKPAD * GNPAD];        // padded Bmat = W_ih rearranged/transposed
__device__ float g_bias[1200];
__device__ __align__(16) float g_h[B_SZ * HIDN];
__device__ float g_pool[B_SZ * HIDN];
__device__ unsigned g_count;   // zero-init; self-resetting
__device__ unsigned g_gen;     // monotonic generation (equality-compared; wrap-safe)

// ------------------------------- prep ---------------------------------------
// Bmat[k][n] : n<1200 -> W_ih[n][k] ; n>=1200 -> W_ih[n-1200][300+k] ; zero-padded
__global__ void prep_kernel(const float* __restrict__ W_ih,
                            const float* __restrict__ b_ih,
                            const float* __restrict__ b_hh) {
    int idx = blockIdx.x * blockDim.x + threadIdx.x;
    int total = GKPAD * GNPAD;
    if (idx < total) {
        int k = idx / GNPAD, n = idx - k * GNPAD;
        float v = 0.f;
        if (k < GK && n < GN) {
            v = (n < 1200) ? W_ih[n * 600 + k] : W_ih[(n - 1200) * 600 + 300 + k];
        }
        g_B[idx] = v;
    }
    if (idx < 1200) g_bias[idx] = b_ih[idx] + b_hh[idx];
}

// --------------------------- vocab GEMM -------------------------------------
// g_V[50000,2400] = glove[50000,300] @ Bmat[300,2400]
__global__ void __launch_bounds__(256) gemm_v_kernel(const float* __restrict__ A) {
    __shared__ float As[8][132];
    __shared__ float Bs[8][132];
    int tid = threadIdx.x;
    int n0 = blockIdx.x * 128;
    int m0 = blockIdx.y * 128;
    int tx = tid & 15, ty = tid >> 4;

    float acc[8][8];
#pragma unroll
    for (int i = 0; i < 8; i++)
#pragma unroll
        for (int j = 0; j < 8; j++) acc[i][j] = 0.f;

    int arow = tid >> 1;          // 0..127
    int ak   = (tid & 1) * 4;     // 0 or 4
    int brow = tid >> 5;          // 0..7
    int bcol = (tid & 31) * 4;    // 0..124

    for (int k0 = 0; k0 < GKPAD; k0 += 8) {
        float4 av = make_float4(0.f, 0.f, 0.f, 0.f);
        int ar = m0 + arow;
        int akk = k0 + ak;
        if (ar < VOCAB && akk < GK)
            av = *(const float4*)(A + (size_t)ar * GK + akk);
        As[ak + 0][arow] = av.x;
        As[ak + 1][arow] = av.y;
        As[ak + 2][arow] = av.z;
        As[ak + 3][arow] = av.w;
        float4 bv = *(const float4*)(g_B + (size_t)(k0 + brow) * GNPAD + n0 + bcol);
        *(float4*)&Bs[brow][bcol] = bv;
        __syncthreads();
#pragma unroll
        for (int k = 0; k < 8; k++) {
            float a[8], b[8];
            *(float4*)(a)     = *(const float4*)&As[k][ty * 4];
            *(float4*)(a + 4) = *(const float4*)&As[k][64 + ty * 4];
            *(float4*)(b)     = *(const float4*)&Bs[k][tx * 4];
            *(float4*)(b + 4) = *(const float4*)&Bs[k][64 + tx * 4];
#pragma unroll
            for (int i = 0; i < 8; i++)
#pragma unroll
                for (int j = 0; j < 8; j++)
                    acc[i][j] = fmaf(a[i], b[j], acc[i][j]);
        }
        __syncthreads();
    }
#pragma unroll
    for (int i = 0; i < 8; i++) {
        int r = m0 + ((i < 4) ? (ty * 4 + i) : (64 + ty * 4 + (i - 4)));
        if (r >= VOCAB) continue;
        float* crow = g_V + (size_t)r * GN;
        int c1 = n0 + tx * 4;                       // always < 2400
        *(float4*)(crow + c1) = make_float4(acc[i][0], acc[i][1], acc[i][2], acc[i][3]);
        int c2 = n0 + 64 + tx * 4;
        if (c2 < GN)
            *(float4*)(crow + c2) = make_float4(acc[i][4], acc[i][5], acc[i][6], acc[i][7]);
    }
}

// ------------------------------ LSTM ----------------------------------------
__device__ __forceinline__ float sigf(float x) { return 1.f / (1.f + __expf(-x)); }

__device__ __forceinline__ void grid_barrier() {
    __syncthreads();
    if (threadIdx.x == 0) {
        __threadfence();
        unsigned my = *(volatile unsigned*)&g_gen;
        if (atomicAdd(&g_count, 1u) == NBLK - 1u) {
            *(volatile unsigned*)&g_count = 0u;
            __threadfence();
            atomicExch(&g_gen, my + 1u);
        } else {
            while (*(volatile unsigned*)&g_gen == my) { }
            __threadfence();
        }
    }
    __syncthreads();
}

// 120 persistent blocks: block = (row tile rt of 64 batch rows) x (unit tile ut of 10 hidden units)
// per step: gates tile [64 x 40] = h_tile[64,300] @ Whh_slice^T + gathered input gates + bias
// smem: W_s 40x308, h_s 64x308 (float4 k-vectors, stride 308 for bank spread), gates 64x42
#define LSTM_SMEM ((40 * 308 + 64 * 308 + 64 * 42) * 4)

__global__ void __launch_bounds__(256, 1) lstm_kernel(const int* __restrict__ ids,
                                                      const float* __restrict__ W_hh) {
    extern __shared__ float sm[];
    float* W_s  = sm;                  // 40*308
    float* h_s  = sm + 40 * 308;       // 64*308
    float* gt_s = sm + 104 * 308;      // 64*42
    __shared__ float bias_s[40];

    const int tid = threadIdx.x;
    const int bid = blockIdx.x;
    const int rt = bid / 30, ut = bid - rt * 30;
    const int rowbase = rt * 64;
    const int u0 = ut * 10;

    // load W_hh slice for this block's 40 gate columns (persistent across all steps)
    for (int i = tid; i < 40 * 300; i += 256) {
        int cc = i / 300, k = i - cc * 300;
        int g = cc / 10;
        int j = g * 300 + u0 + (cc - g * 10);
        W_s[cc * 308 + k] = W_hh[j * 300 + k];
    }
    if (tid < 40) {
        int g = tid / 10;
        bias_s[tid] = g_bias[g * 300 + u0 + (tid - g * 10)];
    }
    // zero this block's slice of h state
    for (int i = tid; i < 640; i += 256) {
        int r = i / 10, u = i - r * 10;
        g_h[(rowbase + r) * 300 + u0 + u] = 0.f;
    }

    const int rp = tid >> 3;            // 0..31 -> rows 2rp, 2rp+1
    const int cg = tid & 7;             // 0..7  -> cols 5cg..5cg+4
    const int r0 = rp * 2;
    const int c0 = cg * 5;
    const int jbase = (cg >> 1) * 300 + u0 + (cg & 1) * 5;   // gate-col -> flat j, consecutive in c

    float c_st[3] = {0.f, 0.f, 0.f};
    float pool[3] = {0.f, 0.f, 0.f};

    grid_barrier();   // h zeros visible everywhere

    const float4* __restrict__ gh4 = (const float4*)g_h;
    float4* h4 = (float4*)h_s;
    const float4* w4 = (const float4*)W_s + (size_t)c0 * 77;

    for (int t = 0; t < T_SZ; t++) {
        // stage h tile [64 x 300] -> smem (stride 77 float4)
        for (int i = tid; i < 64 * 75; i += 256) {
            int r = i / 75, q = i - r * 75;
            h4[r * 77 + q] = gh4[(rowbase + r) * 75 + q];
        }
        __syncthreads();

        float acc[2][5];
#pragma unroll
        for (int r = 0; r < 2; r++)
#pragma unroll
            for (int c = 0; c < 5; c++) acc[r][c] = 0.f;

        const float4* ha = (const float4*)h_s + (size_t)r0 * 77;
        const float4* hb = ha + 77;
#pragma unroll 5
        for (int kq = 0; kq < 75; kq++) {
            float4 h0 = ha[kq];
            float4 h1 = hb[kq];
#pragma unroll
            for (int c = 0; c < 5; c++) {
                float4 w = w4[c * 77 + kq];
                acc[0][c] = fmaf(h0.x, w.x, acc[0][c]);
                acc[0][c] = fmaf(h0.y, w.y, acc[0][c]);
                acc[0][c] = fmaf(h0.z, w.z, acc[0][c]);
                acc[0][c] = fmaf(h0.w, w.w, acc[0][c]);
                acc[1][c] = fmaf(h1.x, w.x, acc[1][c]);
                acc[1][c] = fmaf(h1.y, w.y, acc[1][c]);
                acc[1][c] = fmaf(h1.z, w.z, acc[1][c]);
                acc[1][c] = fmaf(h1.w, w.w, acc[1][c]);
            }
        }

        // epilogue: + bias + gathered input-gate rows (Va at t unless t==511; Vb at t-1 unless t==0)
#pragma unroll
        for (int r = 0; r < 2; r++) {
            int b = rowbase + r0 + r;
            int ia = ids[b * T_SZ + ((t < 511) ? t : 0)];
            int ip = ids[b * T_SZ + ((t > 0) ? (t - 1) : 0)];
            const float* va = g_V + (size_t)ia * GN + jbase;
            const float* vb = g_V + (size_t)ip * GN + 1200 + jbase;
#pragma unroll
            for (int c = 0; c < 5; c++) {
                float v = acc[r][c] + bias_s[c0 + c];
                if (t < 511) v += va[c];
                if (t > 0)   v += vb[c];
                gt_s[(r0 + r) * 42 + c0 + c] = v;
            }
        }
        __syncthreads();

        // elementwise LSTM update; c + pooled sum live in registers (fixed idx mapping)
#pragma unroll
        for (int s = 0; s < 3; s++) {
            int idx = tid + s * 256;
            if (idx < 640) {
                int r = idx / 10, u = idx - r * 10;
                float gi = gt_s[r * 42 + u];
                float gf = gt_s[r * 42 + 10 + u];
                float gg = gt_s[r * 42 + 20 + u];
                float go = gt_s[r * 42 + 30 + u];
                float iv = sigf(gi), fv = sigf(gf), gv = tanhf(gg), ov = sigf(go);
                float cc = fv * c_st[s] + iv * gv;
                c_st[s] = cc;
                float h = ov * tanhf(cc);
                pool[s] += h;
                g_h[(rowbase + r) * 300 + u0 + u] = h;
            }
        }
        grid_barrier();
    }

#pragma unroll
    for (int s = 0; s < 3; s++) {
        int idx = tid + s * 256;
        if (idx < 640) {
            int r = idx / 10, u = idx - r * 10;
            g_pool[(rowbase + r) * 300 + u0 + u] = pool[s] * (1.f / 512.f);
        }
    }
}

// ------------------------------ FC head -------------------------------------
__global__ void fc_kernel(const float* __restrict__ W1, const float* __restrict__ b1,
                          const float* __restrict__ W2, const float* __restrict__ b2,
                          float* __restrict__ out) {
    int b = blockIdx.x;
    __shared__ float p_s[300];
    __shared__ float l1_s[100];
    __shared__ float l2_s[5];
    int tid = threadIdx.x;
    for (int i = tid; i < 300; i += 128) p_s[i] = g_pool[b * 300 + i];
    __syncthreads();
    if (tid < 100) {
        float s = b1[tid];
        const float* wr = W1 + tid * 300;
        for (int k = 0; k < 300; k++) s = fmaf(wr[k], p_s[k], s);
        l1_s[tid] = 1.f / (1.f + expf(-s));
    }
    __syncthreads();
    if (tid < 5) {
        float s = b2[tid];
        const float* wr = W2 + tid * 100;
        for (int k = 0; k < 100; k++) s = fmaf(wr[k], l1_s[k], s);
        l2_s[tid] = 1.f / (1.f + expf(-s));
    }
    __syncthreads();
    if (tid == 0) {
        float m = l2_s[0];
        for (int j = 1; j < 5; j++) m = fmaxf(m, l2_s[j]);
        float sum = 0.f;
        for (int j = 0; j < 5; j++) sum += expf(l2_s[j] - m);
        float lse = m + logf(sum);
        for (int j = 0; j < 5; j++) out[b * 5 + j] = l2_s[j] - lse;
    }
}

// ------------------------------ launch --------------------------------------
extern "C" void kernel_launch(void* const* d_in, const int* in_sizes, int n_in,
                              void* d_out, int out_size) {
    const int*   ids   = (const int*)d_in[0];
    // d_in[1] = max_num_of_words (compile-time 512)
    const float* glove = (const float*)d_in[2];
    const float* W_ih  = (const float*)d_in[3];
    const float* W_hh  = (const float*)d_in[4];
    const float* b_ih  = (const float*)d_in[5];
    const float* b_hh  = (const float*)d_in[6];
    const float* W1    = (const float*)d_in[7];
    const float* b1    = (const float*)d_in[8];
    const float* W2    = (const float*)d_in[9];
    const float* b2    = (const float*)d_in[10];
    float* out = (float*)d_out;

    cudaFuncSetAttribute(lstm_kernel, cudaFuncAttributeMaxDynamicSharedMemorySize, LSTM_SMEM);

    prep_kernel<<<(GKPAD * GNPAD + 255) / 256, 256>>>(W_ih, b_ih, b_hh);
    gemm_v_kernel<<<dim3((GN + 127) / 128, (VOCAB + 127) / 128), 256>>>(glove);
    lstm_kernel<<<NBLK, 256, LSTM_SMEM>>>(ids, W_hh);
    fc_kernel<<<B_SZ, 128>>>(W1, b1, W2, b2, out);
}

// round 6
// speedup vs baseline: 1.1835x; 1.1835x over previous
#include <cuda_runtime.h>
#include <math.h>
#include <stdint.h>

typedef unsigned long long ull;

#define B_SZ   256
#define T_SZ   512
#define HIDN   300
#define VOCAB  50000
#define GN     2400      // [Va | Vb] columns
#define GK     300
#define GKPAD  304
#define GNPAD  2432

// LSTM decomposition: 16 row-groups x 8 CTAs = 128 CTAs
// CTA: 16 batch rows x 38 hidden units (last CTA in group: 34) -> <=152 gate cols (padded 160)
#define NGRP   16
#define GCTA   8
#define WSTR   308       // float stride for W_s / h_s rows (77 float4, odd f4 -> conflict-free)
#define GTSTR  164
#define LSTM_SMEM ((160*WSTR + 16*WSTR + 16*GTSTR) * 4)   // 227,328 B

// -------- device scratch (allocation-free rule: static __device__ arrays) -----
__device__ __align__(16) float g_V[(size_t)VOCAB * GN];   // 480 MB: per-vocab gate tables
__device__ __align__(16) float g_B[GKPAD * GNPAD];        // padded Bmat = W_ih rearranged
__device__ float g_bias[1200];
__device__ __align__(16) float g_hbuf[2][B_SZ * HIDN];    // double-buffered h state
__device__ float g_pool[B_SZ * HIDN];
__device__ unsigned g_cnt[NGRP * 32];    // per-group barrier counters (padded)
__device__ unsigned g_gen2[NGRP * 32];   // per-group generation (monotonic)

// ------------------------- f32x2 packed helpers ------------------------------
__device__ __forceinline__ ull ffma2(ull a, ull b, ull c) {
    ull d;
    asm("fma.rn.f32x2 %0, %1, %2, %3;" : "=l"(d) : "l"(a), "l"(b), "l"(c));
    return d;
}
__device__ __forceinline__ float2 up2(ull v) {
    float2 f;
    asm("mov.b64 {%0, %1}, %2;" : "=f"(f.x), "=f"(f.y) : "l"(v));
    return f;
}
__device__ __forceinline__ ull dup2(float a) {
    ull d;
    asm("mov.b64 %0, {%1, %1};" : "=l"(d) : "f"(a));
    return d;
}

// ------------------------------- prep ---------------------------------------
__global__ void prep_kernel(const float* __restrict__ W_ih,
                            const float* __restrict__ b_ih,
                            const float* __restrict__ b_hh) {
    int idx = blockIdx.x * blockDim.x + threadIdx.x;
    int total = GKPAD * GNPAD;
    if (idx < total) {
        int k = idx / GNPAD, n = idx - k * GNPAD;
        float v = 0.f;
        if (k < GK && n < GN) {
            v = (n < 1200) ? W_ih[n * 600 + k] : W_ih[(n - 1200) * 600 + 300 + k];
        }
        g_B[idx] = v;
    }
    if (idx < 1200) g_bias[idx] = b_ih[idx] + b_hh[idx];
}

// --------------------------- vocab GEMM (FFMA2) ------------------------------
// g_V[50000,2400] = glove[50000,300] @ Bmat[300,2432]
__global__ void __launch_bounds__(256, 2) gemm_v_kernel(const float* __restrict__ A) {
    __shared__ float As[8][132];
    __shared__ float Bs[8][132];
    int tid = threadIdx.x;
    int n0 = blockIdx.x * 128;
    int m0 = blockIdx.y * 128;
    int tx = tid & 15, ty = tid >> 4;

    ull acc[8][4];
#pragma unroll
    for (int i = 0; i < 8; i++)
#pragma unroll
        for (int j = 0; j < 4; j++) acc[i][j] = 0ull;

    int arow = tid >> 1;
    int ak   = (tid & 1) * 4;
    int brow = tid >> 5;
    int bcol = (tid & 31) * 4;

    for (int k0 = 0; k0 < GKPAD; k0 += 8) {
        float4 av = make_float4(0.f, 0.f, 0.f, 0.f);
        int ar = m0 + arow;
        int akk = k0 + ak;
        if (ar < VOCAB && akk < GK)
            av = *(const float4*)(A + (size_t)ar * GK + akk);
        As[ak + 0][arow] = av.x;
        As[ak + 1][arow] = av.y;
        As[ak + 2][arow] = av.z;
        As[ak + 3][arow] = av.w;
        float4 bv = *(const float4*)(g_B + (size_t)(k0 + brow) * GNPAD + n0 + bcol);
        *(float4*)&Bs[brow][bcol] = bv;
        __syncthreads();
#pragma unroll
        for (int k = 0; k < 8; k++) {
            float a[8];
            *(float4*)(a)     = *(const float4*)&As[k][ty * 4];
            *(float4*)(a + 4) = *(const float4*)&As[k][64 + ty * 4];
            ulonglong2 b01 = *(const ulonglong2*)&Bs[k][tx * 4];
            ulonglong2 b23 = *(const ulonglong2*)&Bs[k][64 + tx * 4];
            ull bv0 = b01.x, bv1 = b01.y, bv2 = b23.x, bv3 = b23.y;
#pragma unroll
            for (int i = 0; i < 8; i++) {
                ull ad = dup2(a[i]);
                acc[i][0] = ffma2(ad, bv0, acc[i][0]);
                acc[i][1] = ffma2(ad, bv1, acc[i][1]);
                acc[i][2] = ffma2(ad, bv2, acc[i][2]);
                acc[i][3] = ffma2(ad, bv3, acc[i][3]);
            }
        }
        __syncthreads();
    }
#pragma unroll
    for (int i = 0; i < 8; i++) {
        int r = m0 + ((i < 4) ? (ty * 4 + i) : (64 + ty * 4 + (i - 4)));
        if (r >= VOCAB) continue;
        float* crow = g_V + (size_t)r * GN;
        float2 p0 = up2(acc[i][0]), p1 = up2(acc[i][1]);
        float2 p2 = up2(acc[i][2]), p3 = up2(acc[i][3]);
        int c1 = n0 + tx * 4;                       // always < 2400
        *(float4*)(crow + c1) = make_float4(p0.x, p0.y, p1.x, p1.y);
        int c2 = n0 + 64 + tx * 4;
        if (c2 < GN)
            *(float4*)(crow + c2) = make_float4(p2.x, p2.y, p3.x, p3.y);
    }
}

// ------------------------------ LSTM ----------------------------------------
__device__ __forceinline__ float sigf(float x) { return 1.f / (1.f + __expf(-x)); }

__device__ __forceinline__ void group_barrier(int grp) {
    __syncthreads();
    if (threadIdx.x == 0) {
        __threadfence();
        unsigned* cnt = &g_cnt[grp * 32];
        unsigned* gen = &g_gen2[grp * 32];
        unsigned my = *(volatile unsigned*)gen;
        if (atomicAdd(cnt, 1u) == GCTA - 1u) {
            *(volatile unsigned*)cnt = 0u;
            __threadfence();
            atomicExch(gen, my + 1u);
        } else {
            while (*(volatile unsigned*)gen == my) { }
            __threadfence();
        }
    }
    __syncthreads();
}

// 128 CTAs, 128 threads each. CTA = (group grp of 16 batch rows) x (cid: 38/34 units).
// Thread: rp = tid&7 -> rows 2rp,2rp+1 ; cg = tid>>3 -> gate cols 10cg..10cg+9.
__global__ void __launch_bounds__(128, 1) lstm_kernel(const int* __restrict__ ids,
                                                      const float* __restrict__ W_hh) {
    extern __shared__ float sm[];
    float* W_s  = sm;                      // 160 x 308
    float* h_s  = sm + 160 * WSTR;         // 16 x 308
    float* gt_s = sm + 176 * WSTR;         // 16 x 164
    __shared__ float bias_s[160];

    const int tid = threadIdx.x;
    const int bid = blockIdx.x;
    const int grp = bid >> 3;
    const int cid = bid & 7;
    const int rowbase = grp * 16;
    const int u0 = cid * 38;
    const int nu = (cid == 7) ? 34 : 38;

    // load W_hh slice: col c in [0,160): g=c/40, uu=c%40; zero-pad invalid cols
    for (int i = tid; i < 160 * 300; i += 128) {
        int c = i / 300, k = i - c * 300;
        int g = c / 40, uu = c - g * 40;
        float v = 0.f;
        if (uu < nu) v = W_hh[(g * 300 + u0 + uu) * 300 + k];
        W_s[c * WSTR + k] = v;
    }
    for (int c = tid; c < 160; c += 128) {
        int g = c / 40, uu = c - g * 40;
        bias_s[c] = (uu < nu) ? g_bias[g * 300 + u0 + uu] : 0.f;
    }
    // zero this CTA's slice of h buffer 0
    for (int i = tid; i < 16 * 38; i += 128) {
        int r = i / 38, u = i - r * 38;
        if (u < nu) g_hbuf[0][(rowbase + r) * 300 + u0 + u] = 0.f;
    }

    const int rp = tid & 7;          // rows 2rp, 2rp+1
    const int cg = tid >> 3;         // cols 10cg..10cg+9
    const int gth = cg >> 2;         // gate index (cols stay within one gate: 40%10==0)
    const int uubase = 10 * (cg & 3);
    const int j0 = gth * 300 + u0 + uubase;   // flat gate-col, contiguous over c
    const int b0 = rowbase + 2 * rp;

    float c_st[5] = {0.f, 0.f, 0.f, 0.f, 0.f};
    float pool[5] = {0.f, 0.f, 0.f, 0.f, 0.f};

    group_barrier(grp);    // zeros + W visible / all peers ready

    const ulonglong2* hA = (const ulonglong2*)(h_s + (2 * rp) * WSTR);
    const ulonglong2* hB = (const ulonglong2*)(h_s + (2 * rp + 1) * WSTR);
    const float* wbase = W_s + (10 * cg) * WSTR;

    for (int t = 0; t < T_SZ; t++) {
        // stage h tile [16 x 300] from current buffer (L2 reads, bypass L1)
        const float4* src = (const float4*)(g_hbuf[t & 1] + rowbase * 300);
        for (int i = tid; i < 16 * 75; i += 128) {
            int r = i / 75, q = i - r * 75;
            *(float4*)(h_s + r * WSTR + 4 * q) = __ldcg(src + r * 75 + q);
        }

        // prefetch gathered input-gate values (independent of h -> hidden under GEMM)
        float va[2][10], vb[2][10];
        const bool hasA = (t < 511), hasB = (t > 0);
#pragma unroll
        for (int r = 0; r < 2; r++) {
            int b = b0 + r;
            int iaw = ids[b * T_SZ + (hasA ? t : 0)];
            int ipw = ids[b * T_SZ + (hasB ? (t - 1) : 0)];
            const float* pa = g_V + (size_t)iaw * GN + j0;
            const float* pb = g_V + (size_t)ipw * GN + 1200 + j0;
#pragma unroll
            for (int c = 0; c < 10; c++) {
                bool valid = (uubase + c) < nu;
                va[r][c] = (hasA && valid) ? pa[c] : 0.f;
                vb[r][c] = (hasB && valid) ? pb[c] : 0.f;
            }
        }
        __syncthreads();

        // GEMM: gates[2 rows x 10 cols] += h[2,300] @ W^T, k-paired f32x2
        ull acc[2][10][2];
#pragma unroll
        for (int r = 0; r < 2; r++)
#pragma unroll
            for (int c = 0; c < 10; c++) { acc[r][c][0] = 0ull; acc[r][c][1] = 0ull; }

#pragma unroll 3
        for (int kq = 0; kq < 75; kq++) {
            ulonglong2 h0 = hA[kq];
            ulonglong2 h1 = hB[kq];
#pragma unroll
            for (int c = 0; c < 10; c++) {
                ulonglong2 w = *(const ulonglong2*)(wbase + c * WSTR + 4 * kq);
                acc[0][c][0] = ffma2(h0.x, w.x, acc[0][c][0]);
                acc[0][c][1] = ffma2(h0.y, w.y, acc[0][c][1]);
                acc[1][c][0] = ffma2(h1.x, w.x, acc[1][c][0]);
                acc[1][c][1] = ffma2(h1.y, w.y, acc[1][c][1]);
            }
        }

        // epilogue -> gates smem
#pragma unroll
        for (int r = 0; r < 2; r++) {
#pragma unroll
            for (int c = 0; c < 10; c++) {
                if (uubase + c < nu) {
                    float2 pa2 = up2(acc[r][c][0]);
                    float2 pb2 = up2(acc[r][c][1]);
                    int cabs = 10 * cg + c;
                    float v = (pa2.x + pa2.y) + (pb2.x + pb2.y)
                            + bias_s[cabs] + va[r][c] + vb[r][c];
                    gt_s[(2 * rp + r) * GTSTR + cabs] = v;
                }
            }
        }
        __syncthreads();

        // elementwise LSTM update; c-state + pool in registers (fixed mapping)
        float* dst = g_hbuf[(t + 1) & 1];
#pragma unroll
        for (int s = 0; s < 5; s++) {
            int idx = tid + s * 128;
            if (idx < 16 * 38) {
                int r = idx / 38, u = idx - r * 38;
                if (u < nu) {
                    const float* gb = gt_s + r * GTSTR + u;
                    float gi = gb[0], gf = gb[40], gg = gb[80], go = gb[120];
                    float iv = sigf(gi), fv = sigf(gf), gv = tanhf(gg), ov = sigf(go);
                    float cc = fv * c_st[s] + iv * gv;
                    c_st[s] = cc;
                    float h = ov * tanhf(cc);
                    pool[s] += h;
                    dst[(rowbase + r) * 300 + u0 + u] = h;
                }
            }
        }
        group_barrier(grp);
    }

#pragma unroll
    for (int s = 0; s < 5; s++) {
        int idx = tid + s * 128;
        if (idx < 16 * 38) {
            int r = idx / 38, u = idx - r * 38;
            if (u < nu)
                g_pool[(rowbase + r) * 300 + u0 + u] = pool[s] * (1.f / 512.f);
        }
    }
}

// ------------------------------ FC head -------------------------------------
__global__ void fc_kernel(const float* __restrict__ W1, const float* __restrict__ b1,
                          const float* __restrict__ W2, const float* __restrict__ b2,
                          float* __restrict__ out) {
    int b = blockIdx.x;
    __shared__ float p_s[300];
    __shared__ float l1_s[100];
    __shared__ float l2_s[5];
    int tid = threadIdx.x;
    for (int i = tid; i < 300; i += 128) p_s[i] = g_pool[b * 300 + i];
    __syncthreads();
    if (tid < 100) {
        float s = b1[tid];
        const float* wr = W1 + tid * 300;
        for (int k = 0; k < 300; k++) s = fmaf(wr[k], p_s[k], s);
        l1_s[tid] = 1.f / (1.f + expf(-s));
    }
    __syncthreads();
    if (tid < 5) {
        float s = b2[tid];
        const float* wr = W2 + tid * 100;
        for (int k = 0; k < 100; k++) s = fmaf(wr[k], l1_s[k], s);
        l2_s[tid] = 1.f / (1.f + expf(-s));
    }
    __syncthreads();
    if (tid == 0) {
        float m = l2_s[0];
        for (int j = 1; j < 5; j++) m = fmaxf(m, l2_s[j]);
        float sum = 0.f;
        for (int j = 0; j < 5; j++) sum += expf(l2_s[j] - m);
        float lse = m + logf(sum);
        for (int j = 0; j < 5; j++) out[b * 5 + j] = l2_s[j] - lse;
    }
}

// ------------------------------ launch --------------------------------------
extern "C" void kernel_launch(void* const* d_in, const int* in_sizes, int n_in,
                              void* d_out, int out_size) {
    const int*   ids   = (const int*)d_in[0];
    // d_in[1] = max_num_of_words (compile-time 512)
    const float* glove = (const float*)d_in[2];
    const float* W_ih  = (const float*)d_in[3];
    const float* W_hh  = (const float*)d_in[4];
    const float* b_ih  = (const float*)d_in[5];
    const float* b_hh  = (const float*)d_in[6];
    const float* W1    = (const float*)d_in[7];
    const float* b1    = (const float*)d_in[8];
    const float* W2    = (const float*)d_in[9];
    const float* b2    = (const float*)d_in[10];
    float* out = (float*)d_out;

    cudaFuncSetAttribute(lstm_kernel, cudaFuncAttributeMaxDynamicSharedMemorySize, LSTM_SMEM);

    prep_kernel<<<(GKPAD * GNPAD + 255) / 256, 256>>>(W_ih, b_ih, b_hh);
    gemm_v_kernel<<<dim3((GN + 127) / 128, (VOCAB + 127) / 128), 256>>>(glove);
    lstm_kernel<<<NGRP * GCTA, 128, LSTM_SMEM>>>(ids, W_hh);
    fc_kernel<<<B_SZ, 128>>>(W1, b1, W2, b2, out);
}